// round 1
// baseline (speedup 1.0000x reference)
#include <cuda_runtime.h>
#include <math.h>

#define NN 100000   // nodes
#define NR 4        // relations
#define NE 250000   // edges per relation
#define DD 128      // feature dim

// Scratch (allocation-free rule: __device__ globals)
__device__ __align__(16) float g_agg[(size_t)NR * NN * DD]; // 204.8 MB
__device__ __align__(16) float g_deg[NR * NN];              // 1.6 MB

// ---------------------------------------------------------------------------
// Zero scratch
// ---------------------------------------------------------------------------
__global__ void zero_kernel() {
    size_t stride = (size_t)gridDim.x * blockDim.x;
    size_t i0 = (size_t)blockIdx.x * blockDim.x + threadIdx.x;
    float4* a4 = reinterpret_cast<float4*>(g_agg);
    const size_t n4 = (size_t)NR * NN * DD / 4;
    for (size_t i = i0; i < n4; i += stride) a4[i] = make_float4(0.f, 0.f, 0.f, 0.f);
    float4* d4 = reinterpret_cast<float4*>(g_deg);
    const size_t m4 = (size_t)NR * NN / 4;
    for (size_t i = i0; i < m4; i += stride) d4[i] = make_float4(0.f, 0.f, 0.f, 0.f);
}

// ---------------------------------------------------------------------------
// Edge scatter: one warp per edge. Gather x[src] (L2-resident), vector
// reduction-add into agg[r][dst], degree count by lane 0.
// ---------------------------------------------------------------------------
__global__ void scatter_kernel(const float* __restrict__ x,
                               const int* __restrict__ src,
                               const int* __restrict__ dst) {
    unsigned wid  = (blockIdx.x * blockDim.x + threadIdx.x) >> 5;
    unsigned lane = threadIdx.x & 31;
    if (wid >= (unsigned)(NR * NE)) return;
    int s = src[wid];
    int d = dst[wid];
    unsigned r = wid / NE;

    float4 v = reinterpret_cast<const float4*>(x)[(size_t)s * (DD / 4) + lane];
    float* p = g_agg + ((size_t)r * NN + d) * DD + lane * 4;
    asm volatile("red.global.add.v4.f32 [%0], {%1,%2,%3,%4};"
                 :: "l"(p), "f"(v.x), "f"(v.y), "f"(v.z), "f"(v.w)
                 : "memory");
    if (lane == 0) atomicAdd(&g_deg[r * NN + d], 1.0f);
}

// ---------------------------------------------------------------------------
// Packed fp32x2 helpers (FFMA2 — full-rate fma pipe on sm_103a; FFMA-3reg is
// half-rate). Only reachable via PTX fma.rn.f32x2.
// ---------------------------------------------------------------------------
__device__ __forceinline__ unsigned long long pk2(float a, float b) {
    unsigned long long r;
    asm("mov.b64 %0, {%1,%2};" : "=l"(r) : "f"(a), "f"(b));
    return r;
}
__device__ __forceinline__ void fma2(unsigned long long& d,
                                     unsigned long long a,
                                     unsigned long long b) {
    asm("fma.rn.f32x2 %0, %1, %2, %0;" : "+l"(d) : "l"(a), "l"(b));
}
__device__ __forceinline__ float2 upk2(unsigned long long v) {
    float2 r;
    asm("mov.b64 {%0,%1}, %2;" : "=f"(r.x), "=f"(r.y) : "l"(v));
    return r;
}

// ---------------------------------------------------------------------------
// Fused 5-way GEMM + epilogue.
// Block: 256 threads, tile = 64 rows x 128 cols, K = 128.
// Stages 0..3: h_r = relu((agg_r/deg_r) @ W_r + b_r), accumulated into hsum.
// Stage 4:     acc = x @ loop_weight.
// Final:       out = relu(silu(hsum/4) + acc + node_bias).
// smem: A tile 32 KB + W 64 KB = 96 KB (dynamic).
// ---------------------------------------------------------------------------
__global__ __launch_bounds__(256)
void gemm_fused(const float* __restrict__ x,
                const float* __restrict__ weight,
                const float* __restrict__ conv_bias,
                const float* __restrict__ loop_weight,
                const float* __restrict__ node_bias,
                float* __restrict__ out) {
    extern __shared__ float smem[];
    float4* As4 = reinterpret_cast<float4*>(smem);      // 64 rows x 32 float4
    float* Ws = smem + 64 * DD;                          // 128 x 128 floats
    float4* Ws4 = reinterpret_cast<float4*>(Ws);
    const ulonglong2* Wsu = reinterpret_cast<const ulonglong2*>(Ws);

    const int tid  = threadIdx.x;
    const int lane = tid & 31;
    const int warp = tid >> 5;
    const int base = blockIdx.x * 64;

    float hsum[8][4];
#pragma unroll
    for (int i = 0; i < 8; i++)
#pragma unroll
        for (int j = 0; j < 4; j++) hsum[i][j] = 0.f;

    unsigned long long acc[8][2];

    for (int stage = 0; stage < 5; stage++) {
        __syncthreads();
        // --- load A tile (64 x 128), degree-normalized for relation stages ---
#pragma unroll
        for (int it = 0; it < 8; it++) {
            int lin = tid + it * 256;   // 0..2047
            int row = lin >> 5;
            int c4  = lin & 31;
            int gr  = base + row;
            float4 v = make_float4(0.f, 0.f, 0.f, 0.f);
            if (gr < NN) {
                if (stage < 4) {
                    v = reinterpret_cast<const float4*>(g_agg)
                            [((size_t)stage * NN + gr) * 32 + c4];
                    float rd = 1.0f / fmaxf(g_deg[stage * NN + gr], 1.0f);
                    v.x *= rd; v.y *= rd; v.z *= rd; v.w *= rd;
                } else {
                    v = reinterpret_cast<const float4*>(x)[(size_t)gr * 32 + c4];
                }
            }
            As4[row * 32 + c4] = v;
        }
        // --- load W (128 x 128), L2-resident across blocks ---
        const float4* Wg4 = reinterpret_cast<const float4*>(
            stage < 4 ? weight + (size_t)stage * DD * DD : loop_weight);
#pragma unroll
        for (int it = 0; it < 16; it++)
            Ws4[tid + it * 256] = Wg4[tid + it * 256];
        __syncthreads();

#pragma unroll
        for (int i = 0; i < 8; i++) { acc[i][0] = 0ULL; acc[i][1] = 0ULL; }

        // --- mainloop: K=128 as 32 float4 chunks ---
        for (int k4 = 0; k4 < 32; k4++) {
            float4 a[8];
#pragma unroll
            for (int i = 0; i < 8; i++)
                a[i] = As4[(warp + i * 8) * 32 + k4];   // broadcast LDS
#pragma unroll
            for (int kk = 0; kk < 4; kk++) {
                ulonglong2 wp = Wsu[(k4 * 4 + kk) * 32 + lane];  // LDS.128, conflict-free
#pragma unroll
                for (int i = 0; i < 8; i++) {
                    float av = (kk == 0) ? a[i].x : (kk == 1) ? a[i].y
                             : (kk == 2) ? a[i].z : a[i].w;
                    unsigned long long av2 = pk2(av, av);
                    fma2(acc[i][0], av2, wp.x);
                    fma2(acc[i][1], av2, wp.y);
                }
            }
        }

        // --- per-relation epilogue: relu(acc + bias) accumulated ---
        if (stage < 4) {
            float4 cb = reinterpret_cast<const float4*>(conv_bias + stage * DD)[lane];
#pragma unroll
            for (int i = 0; i < 8; i++) {
                float2 p0 = upk2(acc[i][0]);
                float2 p1 = upk2(acc[i][1]);
                hsum[i][0] += fmaxf(p0.x + cb.x, 0.f);
                hsum[i][1] += fmaxf(p0.y + cb.y, 0.f);
                hsum[i][2] += fmaxf(p1.x + cb.z, 0.f);
                hsum[i][3] += fmaxf(p1.y + cb.w, 0.f);
            }
        }
    }

    // --- final epilogue: mean, SiLU, + self-loop + node bias, ReLU ---
    float4 nb = reinterpret_cast<const float4*>(node_bias)[lane];
#pragma unroll
    for (int i = 0; i < 8; i++) {
        int gr = base + warp + i * 8;
        if (gr < NN) {
            float2 l0 = upk2(acc[i][0]);
            float2 l1 = upk2(acc[i][1]);
            float4 o;
            float h;
            h = hsum[i][0] * 0.25f; h = h / (1.f + __expf(-h));
            o.x = fmaxf(h + l0.x + nb.x, 0.f);
            h = hsum[i][1] * 0.25f; h = h / (1.f + __expf(-h));
            o.y = fmaxf(h + l0.y + nb.y, 0.f);
            h = hsum[i][2] * 0.25f; h = h / (1.f + __expf(-h));
            o.z = fmaxf(h + l1.x + nb.z, 0.f);
            h = hsum[i][3] * 0.25f; h = h / (1.f + __expf(-h));
            o.w = fmaxf(h + l1.y + nb.w, 0.f);
            reinterpret_cast<float4*>(out)[(size_t)gr * 32 + lane] = o;
        }
    }
}

// ---------------------------------------------------------------------------
extern "C" void kernel_launch(void* const* d_in, const int* in_sizes, int n_in,
                              void* d_out, int out_size) {
    const float* x           = (const float*)d_in[0];
    const float* weight      = (const float*)d_in[1];
    const float* conv_bias   = (const float*)d_in[2];
    const float* loop_weight = (const float*)d_in[3];
    const float* node_bias   = (const float*)d_in[4];
    const int*   src         = (const int*)d_in[5];
    const int*   dst         = (const int*)d_in[6];
    float* out = (float*)d_out;

    zero_kernel<<<1024, 256>>>();

    // 1M edges, 1 warp each -> 32M threads -> 125000 blocks
    scatter_kernel<<<(NR * NE * 32) / 256, 256>>>(x, src, dst);

    const int smem_bytes = (64 * DD + DD * DD) * sizeof(float);  // 96 KB
    cudaFuncSetAttribute(gemm_fused,
                         cudaFuncAttributeMaxDynamicSharedMemorySize, smem_bytes);
    gemm_fused<<<(NN + 63) / 64, 256, smem_bytes>>>(
        x, weight, conv_bias, loop_weight, node_bias, out);
}

// round 2
// speedup vs baseline: 1.1610x; 1.1610x over previous
#include <cuda_runtime.h>
#include <math.h>

#define NN 100000   // nodes
#define NR 4        // relations
#define NE 250000   // edges per relation
#define DD 128      // feature dim
#define NSEG (NR * NN)          // 400000 segments
#define NBLK ((NSEG + 1023) / 1024)   // 391 scan blocks

// Scratch (allocation-free rule: __device__ globals)
__device__ __align__(16) float g_agg[(size_t)NR * NN * DD]; // 204.8 MB, written once by gather
__device__ int g_cnt[NSEG];        // histogram
__device__ int g_off[NSEG];        // exclusive-scan start offsets
__device__ int g_cur[NSEG];        // placement cursors (== end offsets after placement)
__device__ int g_ssrc[NR * NE];    // src ids sorted by (rel,dst)
__device__ int g_bsum[512];        // scan block sums

// ---------------------------------------------------------------------------
// CSR build: zero counts -> histogram -> 3-pass scan -> placement
// ---------------------------------------------------------------------------
__global__ void zero_cnt_kernel() {
    int i = blockIdx.x * blockDim.x + threadIdx.x;
    if (i < NSEG) g_cnt[i] = 0;
    if (i < 512) g_bsum[i] = 0;
}

__global__ void hist_kernel(const int* __restrict__ dst) {
    int e = blockIdx.x * blockDim.x + threadIdx.x;
    if (e >= NR * NE) return;
    int r = e / NE;
    atomicAdd(&g_cnt[r * NN + dst[e]], 1);
}

__global__ void scan1_kernel() {
    __shared__ int sh[1024];
    int gi = blockIdx.x * 1024 + threadIdx.x;
    int v = (gi < NSEG) ? g_cnt[gi] : 0;
    sh[threadIdx.x] = v;
    __syncthreads();
#pragma unroll
    for (int o = 1; o < 1024; o <<= 1) {
        int t = (threadIdx.x >= o) ? sh[threadIdx.x - o] : 0;
        __syncthreads();
        sh[threadIdx.x] += t;
        __syncthreads();
    }
    if (gi < NSEG) g_off[gi] = sh[threadIdx.x] - v;   // exclusive
    if (threadIdx.x == 1023) g_bsum[blockIdx.x] = sh[1023];
}

__global__ void scan2_kernel() {    // single block of 512 threads
    __shared__ int sh[512];
    int v = (threadIdx.x < NBLK) ? g_bsum[threadIdx.x] : 0;
    sh[threadIdx.x] = v;
    __syncthreads();
#pragma unroll
    for (int o = 1; o < 512; o <<= 1) {
        int t = (threadIdx.x >= o) ? sh[threadIdx.x - o] : 0;
        __syncthreads();
        sh[threadIdx.x] += t;
        __syncthreads();
    }
    if (threadIdx.x < NBLK) g_bsum[threadIdx.x] = sh[threadIdx.x] - v;  // exclusive
}

__global__ void scan3_kernel() {
    int gi = blockIdx.x * 1024 + threadIdx.x;
    if (gi < NSEG) {
        int o = g_off[gi] + g_bsum[blockIdx.x];
        g_off[gi] = o;
        g_cur[gi] = o;
    }
}

__global__ void place_kernel(const int* __restrict__ src,
                             const int* __restrict__ dst) {
    int e = blockIdx.x * blockDim.x + threadIdx.x;
    if (e >= NR * NE) return;
    int r = e / NE;
    int pos = atomicAdd(&g_cur[r * NN + dst[e]], 1);
    g_ssrc[pos] = src[e];
}

// ---------------------------------------------------------------------------
// Gather: one warp per (rel,node). Sum neighbor rows of x (L2-resident),
// normalize by degree, write agg once. No fp32 atomics anywhere.
// ---------------------------------------------------------------------------
__global__ void gather_kernel(const float* __restrict__ x) {
    unsigned wid  = (blockIdx.x * blockDim.x + threadIdx.x) >> 5;
    unsigned lane = threadIdx.x & 31;
    if (wid >= (unsigned)NSEG) return;
    int beg = g_off[wid];
    int end = g_cur[wid];           // cursor after placement == end offset
    const float4* x4 = reinterpret_cast<const float4*>(x);
    float4 a0 = make_float4(0.f, 0.f, 0.f, 0.f);
    float4 a1 = make_float4(0.f, 0.f, 0.f, 0.f);
    int e = beg;
    for (; e + 1 < end; e += 2) {       // 2-way for MLP on the s->x chain
        int s0 = __ldg(&g_ssrc[e]);
        int s1 = __ldg(&g_ssrc[e + 1]);
        float4 v0 = x4[(size_t)s0 * 32 + lane];
        float4 v1 = x4[(size_t)s1 * 32 + lane];
        a0.x += v0.x; a0.y += v0.y; a0.z += v0.z; a0.w += v0.w;
        a1.x += v1.x; a1.y += v1.y; a1.z += v1.z; a1.w += v1.w;
    }
    if (e < end) {
        int s0 = __ldg(&g_ssrc[e]);
        float4 v0 = x4[(size_t)s0 * 32 + lane];
        a0.x += v0.x; a0.y += v0.y; a0.z += v0.z; a0.w += v0.w;
    }
    float rd = 1.0f / fmaxf((float)(end - beg), 1.0f);
    float4 o;
    o.x = (a0.x + a1.x) * rd;
    o.y = (a0.y + a1.y) * rd;
    o.z = (a0.z + a1.z) * rd;
    o.w = (a0.w + a1.w) * rd;
    reinterpret_cast<float4*>(g_agg)[(size_t)wid * 32 + lane] = o;
}

// ---------------------------------------------------------------------------
// Packed fp32x2 helpers (FFMA2 — full-rate fma pipe on sm_103a)
// ---------------------------------------------------------------------------
__device__ __forceinline__ unsigned long long pk2(float a, float b) {
    unsigned long long r;
    asm("mov.b64 %0, {%1,%2};" : "=l"(r) : "f"(a), "f"(b));
    return r;
}
__device__ __forceinline__ void fma2(unsigned long long& d,
                                     unsigned long long a,
                                     unsigned long long b) {
    asm("fma.rn.f32x2 %0, %1, %2, %0;" : "+l"(d) : "l"(a), "l"(b));
}
__device__ __forceinline__ float2 upk2(unsigned long long v) {
    float2 r;
    asm("mov.b64 {%0,%1}, %2;" : "=f"(r.x), "=f"(r.y) : "l"(v));
    return r;
}

// ---------------------------------------------------------------------------
// Fused 5-way GEMM + epilogue (A pre-normalized; deg removed).
// Block: 256 threads, tile = 64 rows x 128 cols, K = 128.
// ---------------------------------------------------------------------------
__global__ __launch_bounds__(256)
void gemm_fused(const float* __restrict__ x,
                const float* __restrict__ weight,
                const float* __restrict__ conv_bias,
                const float* __restrict__ loop_weight,
                const float* __restrict__ node_bias,
                float* __restrict__ out) {
    extern __shared__ float smem[];
    float4* As4 = reinterpret_cast<float4*>(smem);      // 64 rows x 32 float4
    float* Ws = smem + 64 * DD;                          // 128 x 128 floats
    float4* Ws4 = reinterpret_cast<float4*>(Ws);
    const ulonglong2* Wsu = reinterpret_cast<const ulonglong2*>(Ws);

    const int tid  = threadIdx.x;
    const int lane = tid & 31;
    const int warp = tid >> 5;
    const int base = blockIdx.x * 64;

    float hsum[8][4];
#pragma unroll
    for (int i = 0; i < 8; i++)
#pragma unroll
        for (int j = 0; j < 4; j++) hsum[i][j] = 0.f;

    unsigned long long acc[8][2];

    for (int stage = 0; stage < 5; stage++) {
        __syncthreads();
        // --- load A tile (64 x 128) ---
#pragma unroll
        for (int it = 0; it < 8; it++) {
            int lin = tid + it * 256;   // 0..2047
            int row = lin >> 5;
            int c4  = lin & 31;
            int gr  = base + row;
            float4 v = make_float4(0.f, 0.f, 0.f, 0.f);
            if (gr < NN) {
                if (stage < 4) {
                    v = reinterpret_cast<const float4*>(g_agg)
                            [((size_t)stage * NN + gr) * 32 + c4];
                } else {
                    v = reinterpret_cast<const float4*>(x)[(size_t)gr * 32 + c4];
                }
            }
            As4[row * 32 + c4] = v;
        }
        // --- load W (128 x 128), L2-resident across blocks ---
        const float4* Wg4 = reinterpret_cast<const float4*>(
            stage < 4 ? weight + (size_t)stage * DD * DD : loop_weight);
#pragma unroll
        for (int it = 0; it < 16; it++)
            Ws4[tid + it * 256] = Wg4[tid + it * 256];
        __syncthreads();

#pragma unroll
        for (int i = 0; i < 8; i++) { acc[i][0] = 0ULL; acc[i][1] = 0ULL; }

        // --- mainloop: K=128 as 32 float4 chunks ---
        for (int k4 = 0; k4 < 32; k4++) {
            float4 a[8];
#pragma unroll
            for (int i = 0; i < 8; i++)
                a[i] = As4[(warp + i * 8) * 32 + k4];   // broadcast LDS
#pragma unroll
            for (int kk = 0; kk < 4; kk++) {
                ulonglong2 wp = Wsu[(k4 * 4 + kk) * 32 + lane];  // LDS.128, conflict-free
#pragma unroll
                for (int i = 0; i < 8; i++) {
                    float av = (kk == 0) ? a[i].x : (kk == 1) ? a[i].y
                             : (kk == 2) ? a[i].z : a[i].w;
                    unsigned long long av2 = pk2(av, av);
                    fma2(acc[i][0], av2, wp.x);
                    fma2(acc[i][1], av2, wp.y);
                }
            }
        }

        // --- per-relation epilogue: relu(acc + bias) accumulated ---
        if (stage < 4) {
            float4 cb = reinterpret_cast<const float4*>(conv_bias + stage * DD)[lane];
#pragma unroll
            for (int i = 0; i < 8; i++) {
                float2 p0 = upk2(acc[i][0]);
                float2 p1 = upk2(acc[i][1]);
                hsum[i][0] += fmaxf(p0.x + cb.x, 0.f);
                hsum[i][1] += fmaxf(p0.y + cb.y, 0.f);
                hsum[i][2] += fmaxf(p1.x + cb.z, 0.f);
                hsum[i][3] += fmaxf(p1.y + cb.w, 0.f);
            }
        }
    }

    // --- final epilogue: mean, SiLU, + self-loop + node bias, ReLU ---
    float4 nb = reinterpret_cast<const float4*>(node_bias)[lane];
#pragma unroll
    for (int i = 0; i < 8; i++) {
        int gr = base + warp + i * 8;
        if (gr < NN) {
            float2 l0 = upk2(acc[i][0]);
            float2 l1 = upk2(acc[i][1]);
            float4 o;
            float h;
            h = hsum[i][0] * 0.25f; h = h / (1.f + __expf(-h));
            o.x = fmaxf(h + l0.x + nb.x, 0.f);
            h = hsum[i][1] * 0.25f; h = h / (1.f + __expf(-h));
            o.y = fmaxf(h + l0.y + nb.y, 0.f);
            h = hsum[i][2] * 0.25f; h = h / (1.f + __expf(-h));
            o.z = fmaxf(h + l1.x + nb.z, 0.f);
            h = hsum[i][3] * 0.25f; h = h / (1.f + __expf(-h));
            o.w = fmaxf(h + l1.y + nb.w, 0.f);
            reinterpret_cast<float4*>(out)[(size_t)gr * 32 + lane] = o;
        }
    }
}

// ---------------------------------------------------------------------------
extern "C" void kernel_launch(void* const* d_in, const int* in_sizes, int n_in,
                              void* d_out, int out_size) {
    const float* x           = (const float*)d_in[0];
    const float* weight      = (const float*)d_in[1];
    const float* conv_bias   = (const float*)d_in[2];
    const float* loop_weight = (const float*)d_in[3];
    const float* node_bias   = (const float*)d_in[4];
    const int*   src         = (const int*)d_in[5];
    const int*   dst         = (const int*)d_in[6];
    float* out = (float*)d_out;

    // CSR build
    zero_cnt_kernel<<<(NSEG + 1023) / 1024, 1024>>>();
    hist_kernel<<<(NR * NE + 255) / 256, 256>>>(dst);
    scan1_kernel<<<NBLK, 1024>>>();
    scan2_kernel<<<1, 512>>>();
    scan3_kernel<<<NBLK, 1024>>>();
    place_kernel<<<(NR * NE + 255) / 256, 256>>>(src, dst);

    // Gather (atomic-free aggregate + normalize)
    gather_kernel<<<(NSEG * 32 + 255) / 256, 256>>>(x);

    // Fused GEMM + epilogue
    const int smem_bytes = (64 * DD + DD * DD) * sizeof(float);  // 96 KB
    cudaFuncSetAttribute(gemm_fused,
                         cudaFuncAttributeMaxDynamicSharedMemorySize, smem_bytes);
    gemm_fused<<<(NN + 63) / 64, 256, smem_bytes>>>(
        x, weight, conv_bias, loop_weight, node_bias, out);
}

// round 4
// speedup vs baseline: 1.7898x; 1.5416x over previous
#include <cuda_runtime.h>
#include <math.h>
#include <stdint.h>

#define NN 100000   // nodes
#define NR 4        // relations
#define NE 250000   // edges per relation
#define DD 128      // feature dim
#define NSEG (NR * NN)                 // 400000 segments
#define NBLK ((NSEG + 1023) / 1024)    // 391 scan blocks

// ---------------------------------------------------------------------------
// Scratch (__device__ globals; allocation-free rule)
// ---------------------------------------------------------------------------
__device__ __align__(16) float g_agg[(size_t)NR * NN * DD]; // tf32-rounded aggregate
__device__ __align__(16) float g_wtf[5 * 16 * 8 * 32 * 4];  // fragment-packed tf32 weights
__device__ int g_cnt[NSEG];
__device__ int g_off[NSEG];
__device__ int g_cur[NSEG];
__device__ int g_ssrc[NR * NE];
__device__ int g_bsum[512];

__device__ __forceinline__ uint32_t tf32_rn(float f) {
    uint32_t u;
    asm("cvt.rn.tf32.f32 %0, %1;" : "=r"(u) : "f"(f));
    return u;
}

// m16n8k8 TF32 mma.sync (family-common PTX; no 'a' features)
__device__ __forceinline__ void mma8(float* d, const uint32_t* a,
                                     uint32_t b0, uint32_t b1) {
    asm volatile(
        "mma.sync.aligned.m16n8k8.row.col.f32.tf32.tf32.f32 "
        "{%0,%1,%2,%3}, {%4,%5,%6,%7}, {%8,%9}, {%0,%1,%2,%3};"
        : "+f"(d[0]), "+f"(d[1]), "+f"(d[2]), "+f"(d[3])
        : "r"(a[0]), "r"(a[1]), "r"(a[2]), "r"(a[3]), "r"(b0), "r"(b1));
}

// ---------------------------------------------------------------------------
// CSR build
// ---------------------------------------------------------------------------
__global__ void zero_cnt_kernel() {
    int i = blockIdx.x * blockDim.x + threadIdx.x;
    if (i < NSEG) g_cnt[i] = 0;
    if (i < 512) g_bsum[i] = 0;
}
__global__ void hist_kernel(const int* __restrict__ dst) {
    int e = blockIdx.x * blockDim.x + threadIdx.x;
    if (e >= NR * NE) return;
    atomicAdd(&g_cnt[(e / NE) * NN + dst[e]], 1);
}
__global__ void scan1_kernel() {
    __shared__ int sh[1024];
    int gi = blockIdx.x * 1024 + threadIdx.x;
    int v = (gi < NSEG) ? g_cnt[gi] : 0;
    sh[threadIdx.x] = v;
    __syncthreads();
#pragma unroll
    for (int o = 1; o < 1024; o <<= 1) {
        int t = (threadIdx.x >= o) ? sh[threadIdx.x - o] : 0;
        __syncthreads();
        sh[threadIdx.x] += t;
        __syncthreads();
    }
    if (gi < NSEG) g_off[gi] = sh[threadIdx.x] - v;
    if (threadIdx.x == 1023) g_bsum[blockIdx.x] = sh[1023];
}
__global__ void scan2_kernel() {
    __shared__ int sh[512];
    int v = (threadIdx.x < NBLK) ? g_bsum[threadIdx.x] : 0;
    sh[threadIdx.x] = v;
    __syncthreads();
#pragma unroll
    for (int o = 1; o < 512; o <<= 1) {
        int t = (threadIdx.x >= o) ? sh[threadIdx.x - o] : 0;
        __syncthreads();
        sh[threadIdx.x] += t;
        __syncthreads();
    }
    if (threadIdx.x < NBLK) g_bsum[threadIdx.x] = sh[threadIdx.x] - v;
}
__global__ void scan3_kernel() {
    int gi = blockIdx.x * 1024 + threadIdx.x;
    if (gi < NSEG) {
        int o = g_off[gi] + g_bsum[blockIdx.x];
        g_off[gi] = o;
        g_cur[gi] = o;
    }
}
__global__ void place_kernel(const int* __restrict__ src,
                             const int* __restrict__ dst) {
    int e = blockIdx.x * blockDim.x + threadIdx.x;
    if (e >= NR * NE) return;
    int pos = atomicAdd(&g_cur[(e / NE) * NN + dst[e]], 1);
    g_ssrc[pos] = src[e];
}

// ---------------------------------------------------------------------------
// Gather: one warp per (rel,node); writes tf32-rounded normalized aggregate.
// ---------------------------------------------------------------------------
__global__ void gather_kernel(const float* __restrict__ x) {
    unsigned wid  = (blockIdx.x * blockDim.x + threadIdx.x) >> 5;
    unsigned lane = threadIdx.x & 31;
    if (wid >= (unsigned)NSEG) return;
    int beg = g_off[wid];
    int end = g_cur[wid];
    const float4* x4 = reinterpret_cast<const float4*>(x);
    float4 a0 = make_float4(0.f, 0.f, 0.f, 0.f);
    float4 a1 = make_float4(0.f, 0.f, 0.f, 0.f);
    int e = beg;
    for (; e + 1 < end; e += 2) {
        int s0 = __ldg(&g_ssrc[e]);
        int s1 = __ldg(&g_ssrc[e + 1]);
        float4 v0 = x4[(size_t)s0 * 32 + lane];
        float4 v1 = x4[(size_t)s1 * 32 + lane];
        a0.x += v0.x; a0.y += v0.y; a0.z += v0.z; a0.w += v0.w;
        a1.x += v1.x; a1.y += v1.y; a1.z += v1.z; a1.w += v1.w;
    }
    if (e < end) {
        int s0 = __ldg(&g_ssrc[e]);
        float4 v0 = x4[(size_t)s0 * 32 + lane];
        a0.x += v0.x; a0.y += v0.y; a0.z += v0.z; a0.w += v0.w;
    }
    float rd = 1.0f / fmaxf((float)(end - beg), 1.0f);
    uint4 o;
    o.x = tf32_rn((a0.x + a1.x) * rd);
    o.y = tf32_rn((a0.y + a1.y) * rd);
    o.z = tf32_rn((a0.z + a1.z) * rd);
    o.w = tf32_rn((a0.w + a1.w) * rd);
    reinterpret_cast<uint4*>(g_agg)[(size_t)wid * 32 + lane] = o;
}

// ---------------------------------------------------------------------------
// Weight prep: pack tf32(W[k][n]) into mma.sync B-fragment order.
// gmem float idx = (((s*16 + t)*8 + j2)*32 + l)*4 + r
//   r0: j=2*j2,   b0 (k = t*8 + l%4)
//   r1: j=2*j2,   b1 (k = t*8 + l%4 + 4)
//   r2: j=2*j2+1, b0
//   r3: j=2*j2+1, b1
//   n = j*8 + l/4
// ---------------------------------------------------------------------------
__global__ void wt_kernel(const float* __restrict__ weight,
                          const float* __restrict__ loop_weight) {
    int idx = blockIdx.x * blockDim.x + threadIdx.x;   // 0 .. 81919
    if (idx >= 5 * 16 * 8 * 32 * 4) return;
    int r  = idx & 3;
    int f4 = idx >> 2;
    int l  = f4 & 31;
    int j2 = (f4 >> 5) & 7;
    int t  = (f4 >> 8) & 15;
    int s  = f4 >> 12;
    int j  = 2 * j2 + (r >> 1);
    int n  = j * 8 + (l >> 2);
    int k  = t * 8 + (l & 3) + 4 * (r & 1);
    const float* W = (s < 4) ? weight + (size_t)s * DD * DD : loop_weight;
    reinterpret_cast<uint32_t*>(g_wtf)[idx] = tf32_rn(W[(size_t)k * DD + n]);
}

// ---------------------------------------------------------------------------
// TF32 mma.sync fused 5-way GEMM + epilogue.
// Block 256 = 4 M-warps x 2 N-warps; tile M=128, N=128, K=128/stage.
// ---------------------------------------------------------------------------
#define LDA 132                                  // padded A row (floats)
#define OFF_BIAS 0
#define OFF_A    4096
#define OFF_W    (OFF_A + 128 * LDA * 4)         // 4096 + 67584
#define SMEM_TOTAL (OFF_W + 65536)               // ~137 KB

__global__ __launch_bounds__(256, 1)
void gemm_mma(const float* __restrict__ x,
              const float* __restrict__ conv_bias,
              const float* __restrict__ node_bias,
              float* __restrict__ out) {
    extern __shared__ char smem[];
    float* sbias = reinterpret_cast<float*>(smem + OFF_BIAS);
    float* As    = reinterpret_cast<float*>(smem + OFF_A);
    const float4* Bf = reinterpret_cast<const float4*>(smem + OFF_W);

    const int tid   = threadIdx.x;
    const int lane  = tid & 31;
    const int warp  = tid >> 5;
    const int mwarp = warp & 3;        // 0..3 (M)
    const int nwarp = warp >> 2;       // 0..1 (N)
    const int mbase = blockIdx.x * 128;
    const int lr    = lane >> 2;       // 0..7
    const int lc    = lane & 3;        // 0..3

    for (int i = tid; i < 512; i += 256) sbias[i] = conv_bias[i];
    for (int i = tid; i < 128; i += 256) sbias[512 + i] = node_bias[i];

    float hsum[2][8][4];
#pragma unroll
    for (int mi = 0; mi < 2; mi++)
#pragma unroll
        for (int j = 0; j < 8; j++)
#pragma unroll
            for (int r = 0; r < 4; r++) hsum[mi][j][r] = 0.f;

    float acc[2][8][4];

    for (int s = 0; s < 5; s++) {
        __syncthreads();
        // --- stage A tile (128 x 128) into padded SMEM ---
        const uint4* Ag = (s < 4)
            ? reinterpret_cast<const uint4*>(g_agg) + (size_t)s * NN * 32
            : reinterpret_cast<const uint4*>(x);
#pragma unroll
        for (int it = 0; it < 16; it++) {
            int lin = tid + it * 256;           // 0..4095
            int row = lin >> 5, k4 = lin & 31;
            int gr = mbase + row;
            uint4 v = make_uint4(0u, 0u, 0u, 0u);
            if (gr < NN) {
                v = Ag[(size_t)gr * 32 + k4];
                if (s == 4) {
                    v.x = tf32_rn(__uint_as_float(v.x));
                    v.y = tf32_rn(__uint_as_float(v.y));
                    v.z = tf32_rn(__uint_as_float(v.z));
                    v.w = tf32_rn(__uint_as_float(v.w));
                }
            }
            *reinterpret_cast<uint4*>(As + row * LDA + k4 * 4) = v;
        }
        // --- stage fragment-packed W (64 KB, L2-hot) ---
        const float4* Wg = reinterpret_cast<const float4*>(g_wtf) + (size_t)s * 4096;
#pragma unroll
        for (int it = 0; it < 16; it++)
            *reinterpret_cast<float4*>(smem + OFF_W + (tid + it * 256) * 16) =
                Wg[tid + it * 256];
        __syncthreads();

#pragma unroll
        for (int mi = 0; mi < 2; mi++)
#pragma unroll
            for (int j = 0; j < 8; j++)
#pragma unroll
                for (int r = 0; r < 4; r++) acc[mi][j][r] = 0.f;

        // --- mainloop: 16 k-steps of K=8 ---
#pragma unroll
        for (int t = 0; t < 16; t++) {
            int kb = t * 8 + lc;
            uint32_t a[2][4];
#pragma unroll
            for (int mi = 0; mi < 2; mi++) {
                int rr = mwarp * 32 + mi * 16 + lr;
                a[mi][0] = __float_as_uint(As[rr * LDA + kb]);
                a[mi][1] = __float_as_uint(As[(rr + 8) * LDA + kb]);
                a[mi][2] = __float_as_uint(As[rr * LDA + kb + 4]);
                a[mi][3] = __float_as_uint(As[(rr + 8) * LDA + kb + 4]);
            }
            float4 b[4];
#pragma unroll
            for (int jj = 0; jj < 4; jj++)
                b[jj] = Bf[(t * 8 + nwarp * 4 + jj) * 32 + lane];
#pragma unroll
            for (int mi = 0; mi < 2; mi++)
#pragma unroll
                for (int jj = 0; jj < 4; jj++) {
                    mma8(acc[mi][2 * jj],     a[mi],
                         __float_as_uint(b[jj].x), __float_as_uint(b[jj].y));
                    mma8(acc[mi][2 * jj + 1], a[mi],
                         __float_as_uint(b[jj].z), __float_as_uint(b[jj].w));
                }
        }

        if (s < 4) {
            // --- per-relation epilogue: relu(acc + bias) accumulated ---
#pragma unroll
            for (int mi = 0; mi < 2; mi++)
#pragma unroll
                for (int j = 0; j < 8; j++) {
                    int col = nwarp * 64 + j * 8 + lc * 2;
                    float b0 = sbias[s * 128 + col];
                    float b1 = sbias[s * 128 + col + 1];
                    hsum[mi][j][0] += fmaxf(acc[mi][j][0] + b0, 0.f);
                    hsum[mi][j][1] += fmaxf(acc[mi][j][1] + b1, 0.f);
                    hsum[mi][j][2] += fmaxf(acc[mi][j][2] + b0, 0.f);
                    hsum[mi][j][3] += fmaxf(acc[mi][j][3] + b1, 0.f);
                }
        } else {
            // --- final epilogue: mean, SiLU, + self-loop + node bias, ReLU ---
#pragma unroll
            for (int mi = 0; mi < 2; mi++) {
                int row = mbase + mwarp * 32 + mi * 16 + lr;
#pragma unroll
                for (int j = 0; j < 8; j++) {
                    int col = nwarp * 64 + j * 8 + lc * 2;
                    float nb0 = sbias[512 + col];
                    float nb1 = sbias[512 + col + 1];
                    float h, o0, o1;
                    if (row < NN) {
                        h = hsum[mi][j][0] * 0.25f;
                        h = h / (1.f + __expf(-h));
                        o0 = fmaxf(h + acc[mi][j][0] + nb0, 0.f);
                        h = hsum[mi][j][1] * 0.25f;
                        h = h / (1.f + __expf(-h));
                        o1 = fmaxf(h + acc[mi][j][1] + nb1, 0.f);
                        *reinterpret_cast<float2*>(out + (size_t)row * DD + col) =
                            make_float2(o0, o1);
                    }
                    if (row + 8 < NN) {
                        h = hsum[mi][j][2] * 0.25f;
                        h = h / (1.f + __expf(-h));
                        o0 = fmaxf(h + acc[mi][j][2] + nb0, 0.f);
                        h = hsum[mi][j][3] * 0.25f;
                        h = h / (1.f + __expf(-h));
                        o1 = fmaxf(h + acc[mi][j][3] + nb1, 0.f);
                        *reinterpret_cast<float2*>(out + (size_t)(row + 8) * DD + col) =
                            make_float2(o0, o1);
                    }
                }
            }
        }
    }
}

// ---------------------------------------------------------------------------
extern "C" void kernel_launch(void* const* d_in, const int* in_sizes, int n_in,
                              void* d_out, int out_size) {
    const float* x           = (const float*)d_in[0];
    const float* weight      = (const float*)d_in[1];
    const float* conv_bias   = (const float*)d_in[2];
    const float* loop_weight = (const float*)d_in[3];
    const float* node_bias   = (const float*)d_in[4];
    const int*   src         = (const int*)d_in[5];
    const int*   dst         = (const int*)d_in[6];
    float* out = (float*)d_out;

    // CSR build
    zero_cnt_kernel<<<(NSEG + 1023) / 1024, 1024>>>();
    hist_kernel<<<(NR * NE + 255) / 256, 256>>>(dst);
    scan1_kernel<<<NBLK, 1024>>>();
    scan2_kernel<<<1, 512>>>();
    scan3_kernel<<<NBLK, 1024>>>();
    place_kernel<<<(NR * NE + 255) / 256, 256>>>(src, dst);

    // Weight fragment pack (tiny)
    wt_kernel<<<(5 * 16 * 8 * 32 * 4 + 255) / 256, 256>>>(weight, loop_weight);

    // Gather (atomic-free aggregate + normalize + tf32 round)
    gather_kernel<<<(NSEG * 32 + 255) / 256, 256>>>(x);

    // Fused tensor-core GEMM + epilogue
    cudaFuncSetAttribute(gemm_mma, cudaFuncAttributeMaxDynamicSharedMemorySize,
                         SMEM_TOTAL);
    gemm_mma<<<(NN + 127) / 128, 256, SMEM_TOTAL>>>(x, conv_bias, node_bias, out);
}

// round 5
// speedup vs baseline: 2.2679x; 1.2671x over previous
#include <cuda_runtime.h>
#include <cuda_fp16.h>
#include <math.h>
#include <stdint.h>

#define NN 100000   // nodes
#define NR 4        // relations
#define NE 250000   // edges per relation
#define DD 128      // feature dim
#define NSEG (NR * NN)                 // 400000 segments
#define NBLK ((NSEG + 1023) / 1024)    // 391 scan blocks

// ---------------------------------------------------------------------------
// Scratch (__device__ globals; allocation-free rule)
// ---------------------------------------------------------------------------
__device__ __align__(16) __half g_aggh[(size_t)NR * NN * DD];  // fp16 aggregate, 102.4MB
__device__ __align__(16) uint32_t g_wtfh[5 * 8 * 16 * 32 * 2]; // f16 fragment-packed W
__device__ int g_cnt[NSEG];
__device__ int g_off[NSEG];
__device__ int g_cur[NSEG];
__device__ int g_ssrc[NR * NE];
__device__ int g_bsum[512];

// m16n8k16 F16 mma.sync (family-common PTX), fp32 accumulate
__device__ __forceinline__ void mma16(float* d, const uint32_t* a,
                                      uint32_t b0, uint32_t b1) {
    asm volatile(
        "mma.sync.aligned.m16n8k16.row.col.f32.f16.f16.f32 "
        "{%0,%1,%2,%3}, {%4,%5,%6,%7}, {%8,%9}, {%0,%1,%2,%3};"
        : "+f"(d[0]), "+f"(d[1]), "+f"(d[2]), "+f"(d[3])
        : "r"(a[0]), "r"(a[1]), "r"(a[2]), "r"(a[3]), "r"(b0), "r"(b1));
}

// ---------------------------------------------------------------------------
// CSR build
// ---------------------------------------------------------------------------
__global__ void zero_cnt_kernel() {
    int i = blockIdx.x * blockDim.x + threadIdx.x;
    if (i < NSEG) g_cnt[i] = 0;
    if (i < 512) g_bsum[i] = 0;
}
__global__ void hist_kernel(const int* __restrict__ dst) {
    int e = blockIdx.x * blockDim.x + threadIdx.x;
    if (e >= NR * NE) return;
    atomicAdd(&g_cnt[(e / NE) * NN + dst[e]], 1);
}
__global__ void scan1_kernel() {
    __shared__ int sh[1024];
    int gi = blockIdx.x * 1024 + threadIdx.x;
    int v = (gi < NSEG) ? g_cnt[gi] : 0;
    sh[threadIdx.x] = v;
    __syncthreads();
#pragma unroll
    for (int o = 1; o < 1024; o <<= 1) {
        int t = (threadIdx.x >= o) ? sh[threadIdx.x - o] : 0;
        __syncthreads();
        sh[threadIdx.x] += t;
        __syncthreads();
    }
    if (gi < NSEG) g_off[gi] = sh[threadIdx.x] - v;
    if (threadIdx.x == 1023) g_bsum[blockIdx.x] = sh[1023];
}
__global__ void scan2_kernel() {
    __shared__ int sh[512];
    int v = (threadIdx.x < NBLK) ? g_bsum[threadIdx.x] : 0;
    sh[threadIdx.x] = v;
    __syncthreads();
#pragma unroll
    for (int o = 1; o < 512; o <<= 1) {
        int t = (threadIdx.x >= o) ? sh[threadIdx.x - o] : 0;
        __syncthreads();
        sh[threadIdx.x] += t;
        __syncthreads();
    }
    if (threadIdx.x < NBLK) g_bsum[threadIdx.x] = sh[threadIdx.x] - v;
}
__global__ void scan3_kernel() {
    int gi = blockIdx.x * 1024 + threadIdx.x;
    if (gi < NSEG) {
        int o = g_off[gi] + g_bsum[blockIdx.x];
        g_off[gi] = o;
        g_cur[gi] = o;
    }
}
__global__ void place_kernel(const int* __restrict__ src,
                             const int* __restrict__ dst) {
    int e = blockIdx.x * blockDim.x + threadIdx.x;
    if (e >= NR * NE) return;
    int pos = atomicAdd(&g_cur[(e / NE) * NN + dst[e]], 1);
    g_ssrc[pos] = src[e];
}

// ---------------------------------------------------------------------------
// Gather: one warp per (rel,node); fp32 accumulate, normalize, store fp16.
// ---------------------------------------------------------------------------
__global__ void gather_kernel(const float* __restrict__ x) {
    unsigned wid  = (blockIdx.x * blockDim.x + threadIdx.x) >> 5;
    unsigned lane = threadIdx.x & 31;
    if (wid >= (unsigned)NSEG) return;
    int beg = g_off[wid];
    int end = g_cur[wid];
    const float4* x4 = reinterpret_cast<const float4*>(x);
    float4 a0 = make_float4(0.f, 0.f, 0.f, 0.f);
    float4 a1 = make_float4(0.f, 0.f, 0.f, 0.f);
    int e = beg;
    for (; e + 1 < end; e += 2) {
        int s0 = __ldg(&g_ssrc[e]);
        int s1 = __ldg(&g_ssrc[e + 1]);
        float4 v0 = x4[(size_t)s0 * 32 + lane];
        float4 v1 = x4[(size_t)s1 * 32 + lane];
        a0.x += v0.x; a0.y += v0.y; a0.z += v0.z; a0.w += v0.w;
        a1.x += v1.x; a1.y += v1.y; a1.z += v1.z; a1.w += v1.w;
    }
    if (e < end) {
        int s0 = __ldg(&g_ssrc[e]);
        float4 v0 = x4[(size_t)s0 * 32 + lane];
        a0.x += v0.x; a0.y += v0.y; a0.z += v0.z; a0.w += v0.w;
    }
    float rd = 1.0f / fmaxf((float)(end - beg), 1.0f);
    union { __half2 h[2]; uint2 u; } p;
    p.h[0] = __floats2half2_rn((a0.x + a1.x) * rd, (a0.y + a1.y) * rd);
    p.h[1] = __floats2half2_rn((a0.z + a1.z) * rd, (a0.w + a1.w) * rd);
    reinterpret_cast<uint2*>(g_aggh)[(size_t)wid * 32 + lane] = p.u;
}

// ---------------------------------------------------------------------------
// Weight prep: pack f16(W[k][n]) in m16n8k16 B-fragment order.
// idx = ((((s*8 + t)*16 + j)*32 + l)*2 + r), r in {b0,b1}
//   n = j*8 + l/4 ;  k = t*16 + 2*(l%4) + 8*r  (half2 = {k, k+1})
// ---------------------------------------------------------------------------
__global__ void wt_kernel(const float* __restrict__ weight,
                          const float* __restrict__ loop_weight) {
    int idx = blockIdx.x * blockDim.x + threadIdx.x;   // 0 .. 40959
    if (idx >= 5 * 8 * 16 * 32 * 2) return;
    int r = idx & 1;
    int l = (idx >> 1) & 31;
    int j = (idx >> 6) & 15;
    int t = (idx >> 10) & 7;
    int s = idx >> 13;
    int n = j * 8 + (l >> 2);
    int k = t * 16 + 2 * (l & 3) + 8 * r;
    const float* W = (s < 4) ? weight + (size_t)s * DD * DD : loop_weight;
    union { __half2 h; uint32_t u; } p;
    p.h = __floats2half2_rn(W[(size_t)k * DD + n], W[(size_t)(k + 1) * DD + n]);
    g_wtfh[idx] = p.u;
}

// ---------------------------------------------------------------------------
// F16 mma.sync fused 5-way GEMM + epilogue.
// Block 256 = 4 M-warps x 2 N-warps; tile M=128, N=128, K=128/stage.
// ---------------------------------------------------------------------------
#define LDAH 136                                  // padded A row (halves)
#define OFF_BIAS 0
#define OFF_A    4096
#define OFF_W    (OFF_A + 128 * LDAH * 2)         // 4096 + 34816 = 38912
#define SMEM_TOTAL (OFF_W + 32768)                // 71680

__global__ __launch_bounds__(256)
void gemm_mma(const float* __restrict__ x,
              const float* __restrict__ conv_bias,
              const float* __restrict__ node_bias,
              float* __restrict__ out) {
    extern __shared__ char smem[];
    float* sbias = reinterpret_cast<float*>(smem + OFF_BIAS);
    __half* As   = reinterpret_cast<__half*>(smem + OFF_A);
    const uint2* Bw = reinterpret_cast<const uint2*>(smem + OFF_W);

    const int tid   = threadIdx.x;
    const int lane  = tid & 31;
    const int warp  = tid >> 5;
    const int mwarp = warp & 3;        // 0..3 (M)
    const int nwarp = warp >> 2;       // 0..1 (N)
    const int mbase = blockIdx.x * 128;
    const int lr    = lane >> 2;       // 0..7
    const int lc    = lane & 3;        // 0..3

    for (int i = tid; i < 512; i += 256) sbias[i] = conv_bias[i];
    for (int i = tid; i < 128; i += 256) sbias[512 + i] = node_bias[i];

    float hsum[2][8][4];
#pragma unroll
    for (int mi = 0; mi < 2; mi++)
#pragma unroll
        for (int j = 0; j < 8; j++)
#pragma unroll
            for (int r = 0; r < 4; r++) hsum[mi][j][r] = 0.f;

    float acc[2][8][4];

    for (int s = 0; s < 5; s++) {
        __syncthreads();
        // --- stage A tile (128 x 128 f16) into padded SMEM ---
        if (s < 4) {
            const uint4* Ag = reinterpret_cast<const uint4*>(g_aggh)
                            + (size_t)s * NN * 16;
#pragma unroll
            for (int it = 0; it < 8; it++) {
                int lin = tid + it * 256;          // 0..2047
                int row = lin >> 4, c8 = lin & 15;
                int gr = mbase + row;
                uint4 v = make_uint4(0u, 0u, 0u, 0u);
                if (gr < NN) v = Ag[(size_t)gr * 16 + c8];
                *reinterpret_cast<uint4*>(As + row * LDAH + c8 * 8) = v;
            }
        } else {
            const float4* Xg = reinterpret_cast<const float4*>(x);
#pragma unroll
            for (int it = 0; it < 16; it++) {
                int lin = tid + it * 256;          // 0..4095
                int row = lin >> 5, c4 = lin & 31;
                int gr = mbase + row;
                float4 v = make_float4(0.f, 0.f, 0.f, 0.f);
                if (gr < NN) v = Xg[(size_t)gr * 32 + c4];
                union { __half2 h[2]; uint2 u; } p;
                p.h[0] = __floats2half2_rn(v.x, v.y);
                p.h[1] = __floats2half2_rn(v.z, v.w);
                *reinterpret_cast<uint2*>(As + row * LDAH + c4 * 4) = p.u;
            }
        }
        // --- stage fragment-packed W (32 KB, L2-hot) ---
        const uint4* Wg = reinterpret_cast<const uint4*>(g_wtfh) + (size_t)s * 2048;
#pragma unroll
        for (int it = 0; it < 8; it++)
            *reinterpret_cast<uint4*>(smem + OFF_W + (tid + it * 256) * 16) =
                Wg[tid + it * 256];
        __syncthreads();

#pragma unroll
        for (int mi = 0; mi < 2; mi++)
#pragma unroll
            for (int j = 0; j < 8; j++)
#pragma unroll
                for (int r = 0; r < 4; r++) acc[mi][j][r] = 0.f;

        // --- mainloop: 8 k-steps of K=16 ---
#pragma unroll
        for (int t = 0; t < 8; t++) {
            int c0 = t * 16 + 2 * lc;
            uint32_t a[2][4];
#pragma unroll
            for (int mi = 0; mi < 2; mi++) {
                int rr = mwarp * 32 + mi * 16 + lr;
                a[mi][0] = *reinterpret_cast<const uint32_t*>(As + rr * LDAH + c0);
                a[mi][1] = *reinterpret_cast<const uint32_t*>(As + (rr + 8) * LDAH + c0);
                a[mi][2] = *reinterpret_cast<const uint32_t*>(As + rr * LDAH + c0 + 8);
                a[mi][3] = *reinterpret_cast<const uint32_t*>(As + (rr + 8) * LDAH + c0 + 8);
            }
            uint2 b[8];
#pragma unroll
            for (int jj = 0; jj < 8; jj++)
                b[jj] = Bw[(t * 16 + nwarp * 8 + jj) * 32 + lane];
#pragma unroll
            for (int mi = 0; mi < 2; mi++)
#pragma unroll
                for (int jj = 0; jj < 8; jj++)
                    mma16(acc[mi][jj], a[mi], b[jj].x, b[jj].y);
        }

        if (s < 4) {
            // --- per-relation epilogue: relu(acc + bias) accumulated ---
#pragma unroll
            for (int mi = 0; mi < 2; mi++)
#pragma unroll
                for (int j = 0; j < 8; j++) {
                    int col = nwarp * 64 + j * 8 + lc * 2;
                    float b0 = sbias[s * 128 + col];
                    float b1 = sbias[s * 128 + col + 1];
                    hsum[mi][j][0] += fmaxf(acc[mi][j][0] + b0, 0.f);
                    hsum[mi][j][1] += fmaxf(acc[mi][j][1] + b1, 0.f);
                    hsum[mi][j][2] += fmaxf(acc[mi][j][2] + b0, 0.f);
                    hsum[mi][j][3] += fmaxf(acc[mi][j][3] + b1, 0.f);
                }
        } else {
            // --- final epilogue: mean, SiLU, + self-loop + node bias, ReLU ---
#pragma unroll
            for (int mi = 0; mi < 2; mi++) {
                int row = mbase + mwarp * 32 + mi * 16 + lr;
#pragma unroll
                for (int j = 0; j < 8; j++) {
                    int col = nwarp * 64 + j * 8 + lc * 2;
                    float nb0 = sbias[512 + col];
                    float nb1 = sbias[512 + col + 1];
                    float h, o0, o1;
                    if (row < NN) {
                        h = hsum[mi][j][0] * 0.25f;
                        h = h / (1.f + __expf(-h));
                        o0 = fmaxf(h + acc[mi][j][0] + nb0, 0.f);
                        h = hsum[mi][j][1] * 0.25f;
                        h = h / (1.f + __expf(-h));
                        o1 = fmaxf(h + acc[mi][j][1] + nb1, 0.f);
                        *reinterpret_cast<float2*>(out + (size_t)row * DD + col) =
                            make_float2(o0, o1);
                    }
                    if (row + 8 < NN) {
                        h = hsum[mi][j][2] * 0.25f;
                        h = h / (1.f + __expf(-h));
                        o0 = fmaxf(h + acc[mi][j][2] + nb0, 0.f);
                        h = hsum[mi][j][3] * 0.25f;
                        h = h / (1.f + __expf(-h));
                        o1 = fmaxf(h + acc[mi][j][3] + nb1, 0.f);
                        *reinterpret_cast<float2*>(out + (size_t)(row + 8) * DD + col) =
                            make_float2(o0, o1);
                    }
                }
            }
        }
    }
}

// ---------------------------------------------------------------------------
extern "C" void kernel_launch(void* const* d_in, const int* in_sizes, int n_in,
                              void* d_out, int out_size) {
    const float* x           = (const float*)d_in[0];
    const float* weight      = (const float*)d_in[1];
    const float* conv_bias   = (const float*)d_in[2];
    const float* loop_weight = (const float*)d_in[3];
    const float* node_bias   = (const float*)d_in[4];
    const int*   src         = (const int*)d_in[5];
    const int*   dst         = (const int*)d_in[6];
    float* out = (float*)d_out;

    // CSR build
    zero_cnt_kernel<<<(NSEG + 1023) / 1024, 1024>>>();
    hist_kernel<<<(NR * NE + 255) / 256, 256>>>(dst);
    scan1_kernel<<<NBLK, 1024>>>();
    scan2_kernel<<<1, 512>>>();
    scan3_kernel<<<NBLK, 1024>>>();
    place_kernel<<<(NR * NE + 255) / 256, 256>>>(src, dst);

    // Weight fragment pack (tiny)
    wt_kernel<<<(5 * 8 * 16 * 32 * 2 + 255) / 256, 256>>>(weight, loop_weight);

    // Gather (atomic-free aggregate + normalize + fp16 store)
    gather_kernel<<<(NSEG * 32 + 255) / 256, 256>>>(x);

    // Fused tensor-core GEMM + epilogue
    cudaFuncSetAttribute(gemm_mma, cudaFuncAttributeMaxDynamicSharedMemorySize,
                         SMEM_TOTAL);
    gemm_mma<<<(NN + 127) / 128, 256, SMEM_TOTAL>>>(x, conv_bias, node_bias, out);
}